// round 13
// baseline (speedup 1.0000x reference)
#include <cuda_runtime.h>
#include <math.h>

#define HH 256
#define WW 256
#define CC 128
#define BIGF 1000000000.0f

// ---------------- device scratch ----------------
__device__ float g_cost[HH*WW*8];
__device__ float g_dist[2][HH*WW];
__device__ float g_geo [HH*WW];
__device__ float g_var [HH*WW];
__device__ float g_abs2[HH*WW];
__device__ float g_omega[HH*WW];
__device__ unsigned g_arrive;
__device__ int g_lastchg[256];        // last phase each block's output changed

__device__ __forceinline__ float softplusf(float x){
    return x > 30.0f ? x : log1pf(expf(x));
}

// packed f32x2 helpers (Blackwell SIMD2 fp32: add/mul/fma only)
__device__ __forceinline__ unsigned long long pk2(float x, float y){
    unsigned long long r;
    asm("mov.b64 %0, {%1, %2};" : "=l"(r) : "f"(x), "f"(y));
    return r;
}
__device__ __forceinline__ void fma2(unsigned long long &d, unsigned long long a,
                                     unsigned long long b){
    asm("fma.rn.f32x2 %0, %1, %2, %0;" : "+l"(d) : "l"(a), "l"(b));
}
__device__ __forceinline__ unsigned long long add2(unsigned long long a,
                                                   unsigned long long b){
    unsigned long long r;
    asm("add.rn.f32x2 %0, %1, %2;" : "=l"(r) : "l"(a), "l"(b));
    return r;
}
__device__ __forceinline__ float2 upk2(unsigned long long v){
    float2 r;
    asm("mov.b64 {%0, %1}, %2;" : "=f"(r.x), "=f"(r.y) : "l"(v));
    return r;
}

// ---------------- fused heuristic + cost + MLP + dist BIG-init ----------------
// DIRS: 0:(-1,-1) 1:(-1,0) 2:(-1,1) 3:(0,-1) 4:(0,1) 5:(1,-1) 6:(1,0) 7:(1,1)
// cost[p][i] == cost[p+d_i][7-i]; compute i=4..7, mirror-write.
__global__ void hc_k(const float* __restrict__ f, float* __restrict__ out,
                     const float* __restrict__ w1, const float* __restrict__ b1,
                     const float* __restrict__ w2, const float* __restrict__ b2,
                     const int* __restrict__ endn){
    extern __shared__ float dyn[];
    float* sw     = dyn;                       // 4096 floats (W1)
    float* sbuf   = dyn + 4096;                // 2 x 5508 floats
    float* snorm  = dyn + 4096 + 11016;        // 324
    float* sendlf = snorm + 324;               // 64

    int tid = threadIdx.x;
    int tx = tid & 15, ty = tid >> 4;
    int bh = blockIdx.y*16, bw = blockIdx.x*16;
    int base = (ty+1)*18 + (tx+1);

    if (tid == 0){
        g_lastchg[blockIdx.y*16 + blockIdx.x] = -1;
        if (blockIdx.x == 0 && blockIdx.y == 0) g_arrive = 0u;
    }

    for (int i = tid; i < 1024; i += 256)
        *(float4*)(sw + i*4) = *(const float4*)(w1 + i*4);
    if (tid < 16){
        int e = endn[0]*WW + endn[1];
        *(float4*)(sendlf + tid*4) = *(const float4*)(f + (size_t)e*CC + tid*4);
    }

    for (int idx = tid; idx < 11016; idx += 256) sbuf[idx] = 0.0f;
    __syncthreads();

    int eidx = -1;
    if (tid < 16)      eidx = (tid+2)*18;            // col 0, rows 2..17
    else if (tid < 33) eidx = (tid-15)*18 + 17;      // col 17, rows 1..17
    else if (tid < 49) eidx = 17*18 + (tid-32);      // row 17, cols 1..16

    float geo = 0.0f, var = 0.0f, ab2 = 0.0f;
    float dot4[4] = {0.f,0.f,0.f,0.f};
    float ownss = 0.0f, ess = 0.0f;

    unsigned long long macc[16];
    #pragma unroll
    for (int j=0;j<16;j++) macc[j] = pk2(b1[2*j], b1[2*j+1]);

    auto issue_chunk = [&](int ck, int bsel){
        int c0 = ck*16;
        float* dst = sbuf + bsel*5508;
        for (int idx = tid; idx < 5184; idx += 256){
            int cell = idx >> 4, ch = idx & 15;
            int r = cell / 18, col = cell - r*18;
            int gh = bh + r - 1, gw = bw + col - 1;
            if ((unsigned)gh < HH && (unsigned)gw < WW){
                unsigned sa = (unsigned)__cvta_generic_to_shared(dst + cell*17 + ch);
                asm volatile("cp.async.ca.shared.global [%0], [%1], 4;\n"
                             :: "r"(sa), "l"(f + (size_t)(gh*WW+gw)*CC + c0 + ch));
            }
        }
        asm volatile("cp.async.commit_group;\n");
    };

    issue_chunk(0, 0);

    for (int ck = 0; ck < 8; ck++){
        asm volatile("cp.async.wait_group 0;\n" ::: "memory");
        __syncthreads();
        if (ck < 7) issue_chunk(ck+1, (ck+1)&1);

        const float* sb = sbuf + (ck&1)*5508;
        int c0 = ck*16;

        #pragma unroll
        for (int ch = 0; ch < 16; ch++){
            float v00 = sb[(base-19)*17+ch], v01 = sb[(base-18)*17+ch], v02 = sb[(base-17)*17+ch];
            float v10 = sb[(base- 1)*17+ch], v11 = sb[(base   )*17+ch], v12 = sb[(base+ 1)*17+ch];
            float v20 = sb[(base+17)*17+ch], v21 = sb[(base+18)*17+ch], v22 = sb[(base+19)*17+ch];
            float gx = (v02 - v00) + 2.0f*(v12 - v10) + (v22 - v20);
            float gy = (v20 - v00) + 2.0f*(v21 - v01) + (v22 - v02);
            geo += sqrtf(gx*gx + gy*gy);
            ownss   = fmaf(v11, v11, ownss);
            dot4[0] = fmaf(v11, v12, dot4[0]);
            dot4[1] = fmaf(v11, v20, dot4[1]);
            dot4[2] = fmaf(v11, v21, dot4[2]);
            dot4[3] = fmaf(v11, v22, dot4[3]);
            {
                unsigned long long f2 = pk2(v11, v11);
                const ulonglong2* wr = (const ulonglong2*)(sw + (c0 + ch)*32);
                #pragma unroll
                for (int q = 0; q < 8; q++){
                    ulonglong2 wv = wr[q];
                    fma2(macc[2*q  ], f2, wv.x);
                    fma2(macc[2*q+1], f2, wv.y);
                }
            }
            int c = c0 + ch;
            if (c >= 64){
                float xs = v00+v01+v02+v10+v11+v12+v20+v21+v22;
                float x2 = v00*v00+v01*v01+v02*v02+v10*v10+v11*v11+v12*v12+v20*v20+v21*v21+v22*v22;
                float m1 = xs * (1.0f/9.0f);
                var += x2 * (1.0f/9.0f) - m1*m1;
            } else {
                float d = v11 - sendlf[c];
                ab2 += d*d;
            }
        }
        if (tid < 49){
            const float* eb = sb + eidx*17;
            #pragma unroll
            for (int ch=0; ch<16; ch++) ess = fmaf(eb[ch], eb[ch], ess);
        }
    }

    int px = (bh+ty)*WW + (bw+tx);
    g_geo [px] = geo * (1.0f/128.0f);
    g_var [px] = var;
    g_abs2[px] = ab2;
    g_dist[0][px] = BIGF;
    g_dist[1][px] = BIGF;

    {
        float z = b2[0];
        #pragma unroll
        for (int j=0;j<16;j++){
            float2 u = upk2(macc[j]);
            z = fmaf(fmaxf(u.x, 0.0f), w2[2*j],   z);
            z = fmaf(fmaxf(u.y, 0.0f), w2[2*j+1], z);
        }
        g_omega[px] = 1.0f / (1.0f + expf(-z));
    }

    __syncthreads();
    snorm[base] = ownss;
    if (tid < 49) snorm[eidx] = ess;
    __syncthreads();

    int h = bh + ty, w = bw + tx;
    float invp = 1.0f / fmaxf(sqrtf(ownss), 1e-12f);
    const int nbo[4] = {1, 17, 18, 19};
    const int ddx[4] = {0,1,1,1};
    const int ddy[4] = {1,-1,0,1};
    #pragma unroll
    for (int d=0; d<4; d++){
        int i = 4 + d;
        int nh = h + ddx[d], nw = w + ddy[d];
        if ((unsigned)nh < HH && (unsigned)nw < WW){
            float nn = snorm[base + nbo[d]];
            float val = 1.0f - dot4[d] * invp / fmaxf(sqrtf(nn), 1e-12f);
            int npx = nh*WW + nw;
            g_cost[(size_t)px *8 + i]          = val;
            out   [(size_t)px *10 + 1 + i]     = val;
            g_cost[(size_t)npx*8 + (7-i)]      = val;
            out   [(size_t)npx*10 + 1 + (7-i)] = val;
        } else {
            g_cost[(size_t)px*8 + i]      = BIGF;
            out   [(size_t)px*10 + 1 + i] = BIGF;
        }
    }
    const int udx[4] = {-1,-1,-1, 0};
    const int udy[4] = {-1, 0, 1,-1};
    #pragma unroll
    for (int j=0; j<4; j++){
        int nh = h + udx[j], nw = w + udy[j];
        if (!((unsigned)nh < HH && (unsigned)nw < WW)){
            g_cost[(size_t)px*8 + j]      = BIGF;
            out   [(size_t)px*10 + 1 + j] = BIGF;
        }
    }
}

// ---------------- persistent relaxation + stability skip + final pack ----------
// 256 blocks x 512 threads, 2/SM. Tile 16x16, halo 8 -> region 32x32.
// cheb skip + stability skip (all 9 of self+neighbors unchanged since <= p-2
// -> output provably identical; skip iterations and stores).
__global__ void __launch_bounds__(512,2) dist_relax_persist(const int* __restrict__ startn,
                                                            const int* __restrict__ endn,
                                                            const float* __restrict__ dl,
                                                            const float* __restrict__ gm,
                                                            const float* __restrict__ bt,
                                                            float* __restrict__ out){
    __shared__ __align__(16) float sd[2][34][36];
    __shared__ int s_skip;
    __shared__ int s_chg;
    int tid = threadIdx.x;
    int tx = tid & 15, ty = tid >> 4;
    int bx = blockIdx.x, by = blockIdx.y;
    int bh = by*16 - 8, bw = bx*16 - 8;
    int bid = by*16 + bx;
    const unsigned NBLK = 256u;

    int sh = startn[0], sw_ = startn[1];
    int d0;
    {
        int rlo = max(bh, 0),  rhi = min(bh+31, HH-1);
        int clo = max(bw, 0),  chi = min(bw+31, WW-1);
        int dr = max(max(rlo - sh, sh - rhi), 0);
        int dc = max(max(clo - sw_, sw_ - chi), 0);
        d0 = max(dr, dc);
    }

    // flag source for threads 0..8 (8 neighbors + self)
    int fbid = -1;
    if (tid < 8){
        const int offy[8] = {-1,-1,-1, 0, 0, 1, 1, 1};
        const int offx[8] = {-1, 0, 1,-1, 1,-1, 0, 1};
        int ny = by + offy[tid], nx = bx + offx[tid];
        if ((unsigned)ny < 16u && (unsigned)nx < 16u) fbid = ny*16 + nx;
    } else if (tid == 8) fbid = bid;

    // BIG frame
    for (int idx = tid; idx < 2*34*36; idx += 512){
        int l = idx / (34*36);
        int rem = idx % (34*36);
        int r = rem / 36, c = rem % 36;
        if (r == 0 || r == 33 || c == 0 || c >= 33)
            sd[l][r][c] = BIGF;
    }

    unsigned long long cst2[8];
    {
        float ca[8], cb[8];
        int gh = bh + ty;
        int gw0 = bw + 2*tx, gw1 = gw0 + 1;
        bool ok0 = (unsigned)gh < HH && (unsigned)gw0 < WW;
        bool ok1 = (unsigned)gh < HH && (unsigned)gw1 < WW;
        #pragma unroll
        for (int i=0;i<8;i++){ ca[i] = BIGF; cb[i] = BIGF; }
        if (ok0){
            const float4* cp = (const float4*)(g_cost + (size_t)(gh*WW+gw0)*8);
            float4 u = __ldg(cp), w = __ldg(cp+1);
            ca[0]=u.x; ca[1]=u.y; ca[2]=u.z; ca[3]=u.w;
            ca[4]=w.x; ca[5]=w.y; ca[6]=w.z; ca[7]=w.w;
        }
        if (ok1){
            const float4* cp = (const float4*)(g_cost + (size_t)(gh*WW+gw1)*8);
            float4 u = __ldg(cp), w = __ldg(cp+1);
            cb[0]=u.x; cb[1]=u.y; cb[2]=u.z; cb[3]=u.w;
            cb[4]=w.x; cb[5]=w.y; cb[6]=w.z; cb[7]=w.w;
        }
        #pragma unroll
        for (int i=0;i<8;i++) cst2[i] = pk2(ca[i], cb[i]);
    }

    // base state in SMEM (BIG except start)
    for (int idx = tid; idx < 1024; idx += 512){
        int r = idx >> 5, c = idx & 31;
        int gh = bh + r, gw = bw + c;
        sd[0][r+1][c+1] = (gh == sh && gw == sw_) ? 0.0f : BIGF;
    }

    bool is_store_thread = (ty >= 8 && ty < 24 && tx >= 4 && tx < 12);
    int gh_s = bh + ty, gw_s = bw + 2*tx;

    #pragma unroll 1
    for (int p = 0; p < 32; p++){
        float* __restrict__ dst = g_dist[(p+1) & 1];
        bool chebskip = (d0 > 8*(p+1));

        if (!chebskip){
            // flag reads (overlap with ring reload)
            int lc = -1;
            if (tid < 9 && fbid >= 0) lc = *((volatile int*)&g_lastchg[fbid]);
            if (tid == 0){ s_chg = 0; }

            if (p > 0){
                const float* __restrict__ src = g_dist[p & 1];
                for (int idx = tid; idx < 768; idx += 512){
                    int r, c;
                    if (idx < 256)      { r = idx >> 5;              c = idx & 31; }
                    else if (idx < 512) { r = 24 + ((idx-256) >> 5); c = idx & 31; }
                    else { int t = idx-512; r = 8 + (t >> 4); int cc = t & 15;
                           c = (cc < 8) ? cc : 16 + cc; }
                    int gh = bh + r, gw = bw + c;
                    float v = BIGF;
                    if ((unsigned)gh < HH && (unsigned)gw < WW)
                        v = __ldcg(src + gh*WW + gw);
                    sd[0][r+1][c+1] = v;
                }
            }
            // warp 0 reduces max(lastchg)
            if (tid < 32){
                #pragma unroll
                for (int off = 16; off; off >>= 1)
                    lc = max(lc, __shfl_xor_sync(0xffffffffu, lc, off));
                if (tid == 0) s_skip = (p >= 2 && lc <= p-2) ? 1 : 0;
            }
            __syncthreads();
            bool sk = (s_skip != 0);

            if (!sk){
                // preload old dst interior values (change detection baseline)
                float old0 = 0.f, old1 = 0.f;
                if (p < 31 && is_store_thread){
                    old0 = __ldcg(dst + gh_s*WW + gw_s);
                    old1 = __ldcg(dst + gh_s*WW + gw_s + 1);
                }

                #pragma unroll
                for (int it = 0; it < 8; it++){
                    const int cur = it & 1;
                    bool act = (ty >= 1+it) && (ty <= 30-it) &&
                               (2*tx+1 >= 1+it) && (2*tx <= 30-it);
                    if (act){
                        unsigned long long a0 = *(const unsigned long long*)&sd[cur][ty  ][2*tx];
                        unsigned long long a1 = *(const unsigned long long*)&sd[cur][ty  ][2*tx+2];
                        unsigned long long b0 = *(const unsigned long long*)&sd[cur][ty+1][2*tx];
                        unsigned long long b1 = *(const unsigned long long*)&sd[cur][ty+1][2*tx+2];
                        unsigned long long c0 = *(const unsigned long long*)&sd[cur][ty+2][2*tx];
                        unsigned long long c1 = *(const unsigned long long*)&sd[cur][ty+2][2*tx+2];

                        float2 fa0 = upk2(a0), fa1 = upk2(a1);
                        float2 fb0 = upk2(b0), fb1 = upk2(b1);
                        float2 fc0 = upk2(c0), fc1 = upk2(c1);

                        unsigned long long mixA = pk2(fa0.y, fa1.x);
                        unsigned long long mixC = pk2(fc0.y, fc1.x);

                        unsigned long long s0 = add2(a0,   cst2[0]);
                        unsigned long long s1 = add2(mixA, cst2[1]);
                        unsigned long long s2 = add2(a1,   cst2[2]);
                        unsigned long long s3 = add2(b0,   cst2[3]);
                        unsigned long long s4 = add2(b1,   cst2[4]);
                        unsigned long long s5 = add2(c0,   cst2[5]);
                        unsigned long long s6 = add2(mixC, cst2[6]);
                        unsigned long long s7 = add2(c1,   cst2[7]);

                        float2 u0 = upk2(s0), u1 = upk2(s1), u2 = upk2(s2), u3 = upk2(s3);
                        float2 u4 = upk2(s4), u5 = upk2(s5), u6 = upk2(s6), u7 = upk2(s7);

                        float v0 = fminf(fb0.y,
                                   fminf(fminf(fminf(u0.x,u1.x), fminf(u2.x,u3.x)),
                                         fminf(fminf(u4.x,u5.x), fminf(u6.x,u7.x))));
                        float v1 = fminf(fb1.x,
                                   fminf(fminf(fminf(u0.y,u1.y), fminf(u2.y,u3.y)),
                                         fminf(fminf(u4.y,u5.y), fminf(u6.y,u7.y))));

                        sd[cur^1][ty+1][2*tx+1] = v0;
                        sd[cur^1][ty+1][2*tx+2] = v1;
                    }
                    __syncthreads();
                }
                // result in sd[0], exact interior rows/cols [8,23]

                if (p < 31){
                    if (is_store_thread){
                        float n0 = sd[0][ty+1][2*tx+1];
                        float n1 = sd[0][ty+1][2*tx+2];
                        __stcg(dst + gh_s*WW + gw_s,     n0);
                        __stcg(dst + gh_s*WW + gw_s + 1, n1);
                        if (n0 != old0 || n1 != old1) s_chg = 1;
                    }
                    __threadfence();
                }
            }

            if (p == 31){
                // final output (valid whether computed or skipped: sd[0] interior
                // always holds this block's current converged output)
                if (is_store_thread){
                    int e = endn[0]*WW + endn[1];
                    float varEnd = g_var[e];
                    float q0 = softplusf(*dl), q1 = softplusf(*gm), q2 = softplusf(*bt);
                    #pragma unroll
                    for (int b=0; b<2; b++){
                        int px = gh_s*WW + gw_s + b;
                        float om = g_omega[px];
                        float hv = q0*g_geo[px]
                                 + om*q1*(varEnd - g_var[px])
                                 + (1.0f - om)*q2*sqrtf(g_abs2[px]);
                        out[(size_t)px*10 + 0] = fmaxf(hv, 0.0f);
                        out[(size_t)px*10 + 9] = fminf(sd[0][ty+1][2*tx+1+b], BIGF);
                    }
                }
            }
        }

        if (p < 31){
            __syncthreads();
            if (tid == 0){
                if (!chebskip && s_chg)
                    *((volatile int*)&g_lastchg[bid]) = p;
                __threadfence();
                atomicAdd(&g_arrive, 1u);
                unsigned target = NBLK * (unsigned)(p + 1);
                while (*((volatile unsigned*)&g_arrive) < target) __nanosleep(64);
            }
            __syncthreads();
        }
    }
}

// ---------------- launch ----------------
extern "C" void kernel_launch(void* const* d_in, const int* in_sizes, int n_in,
                              void* d_out, int out_size){
    const float* f = (const float*)d_in[0];
    float* out = (float*)d_out;

    static int smem_set = 0;
    if (!smem_set){
        cudaFuncSetAttribute(hc_k, cudaFuncAttributeMaxDynamicSharedMemorySize, 62000);
        smem_set = 1;
    }

    hc_k<<<dim3(16,16), 256, 62000>>>(f, out, (const float*)d_in[4], (const float*)d_in[5],
                                      (const float*)d_in[6], (const float*)d_in[7],
                                      (const int*)d_in[9]);
    dist_relax_persist<<<dim3(16,16), 512>>>((const int*)d_in[8], (const int*)d_in[9],
                                             (const float*)d_in[1], (const float*)d_in[2],
                                             (const float*)d_in[3], out);
}

// round 14
// speedup vs baseline: 1.0997x; 1.0997x over previous
#include <cuda_runtime.h>
#include <math.h>

#define HH 256
#define WW 256
#define CC 128
#define BIGF 1000000000.0f

// ---------------- device scratch ----------------
__device__ float g_cost[HH*WW*8];
__device__ float g_dist[2][HH*WW];
__device__ float g_geo [HH*WW];
__device__ float g_var [HH*WW];
__device__ float g_abs2[HH*WW];
__device__ float g_omega[HH*WW];
__device__ unsigned g_arrive;

__device__ __forceinline__ float softplusf(float x){
    return x > 30.0f ? x : log1pf(expf(x));
}

// packed f32x2 helpers (Blackwell SIMD2 fp32: add/mul/fma only)
__device__ __forceinline__ unsigned long long pk2(float x, float y){
    unsigned long long r;
    asm("mov.b64 %0, {%1, %2};" : "=l"(r) : "f"(x), "f"(y));
    return r;
}
__device__ __forceinline__ void fma2(unsigned long long &d, unsigned long long a,
                                     unsigned long long b){
    asm("fma.rn.f32x2 %0, %1, %2, %0;" : "+l"(d) : "l"(a), "l"(b));
}
__device__ __forceinline__ unsigned long long add2(unsigned long long a,
                                                   unsigned long long b){
    unsigned long long r;
    asm("add.rn.f32x2 %0, %1, %2;" : "=l"(r) : "l"(a), "l"(b));
    return r;
}
__device__ __forceinline__ float2 upk2(unsigned long long v){
    float2 r;
    asm("mov.b64 {%0, %1}, %2;" : "=f"(r.x), "=f"(r.y) : "l"(v));
    return r;
}

// ---------------- fused heuristic + cost + MLP + dist BIG-init ----------------
// DIRS: 0:(-1,-1) 1:(-1,0) 2:(-1,1) 3:(0,-1) 4:(0,1) 5:(1,-1) 6:(1,0) 7:(1,1)
// cost[p][i] == cost[p+d_i][7-i]; compute i=4..7, mirror-write.
__global__ void hc_k(const float* __restrict__ f, float* __restrict__ out,
                     const float* __restrict__ w1, const float* __restrict__ b1,
                     const float* __restrict__ w2, const float* __restrict__ b2,
                     const int* __restrict__ endn){
    extern __shared__ float dyn[];
    float* sw     = dyn;                       // 4096 floats (W1)
    float* sbuf   = dyn + 4096;                // 2 x 5508 floats
    float* snorm  = dyn + 4096 + 11016;        // 324
    float* sendlf = snorm + 324;               // 64

    int tid = threadIdx.x;
    int tx = tid & 15, ty = tid >> 4;
    int bh = blockIdx.y*16, bw = blockIdx.x*16;
    int base = (ty+1)*18 + (tx+1);

    if (tid == 0 && blockIdx.x == 0 && blockIdx.y == 0) g_arrive = 0u;

    for (int i = tid; i < 1024; i += 256)
        *(float4*)(sw + i*4) = *(const float4*)(w1 + i*4);
    if (tid < 16){
        int e = endn[0]*WW + endn[1];
        *(float4*)(sendlf + tid*4) = *(const float4*)(f + (size_t)e*CC + tid*4);
    }

    for (int idx = tid; idx < 11016; idx += 256) sbuf[idx] = 0.0f;
    __syncthreads();

    int eidx = -1;
    if (tid < 16)      eidx = (tid+2)*18;            // col 0, rows 2..17
    else if (tid < 33) eidx = (tid-15)*18 + 17;      // col 17, rows 1..17
    else if (tid < 49) eidx = 17*18 + (tid-32);      // row 17, cols 1..16

    float geo = 0.0f, var = 0.0f, ab2 = 0.0f;
    float dot4[4] = {0.f,0.f,0.f,0.f};
    float ownss = 0.0f, ess = 0.0f;

    unsigned long long macc[16];
    #pragma unroll
    for (int j=0;j<16;j++) macc[j] = pk2(b1[2*j], b1[2*j+1]);

    auto issue_chunk = [&](int ck, int bsel){
        int c0 = ck*16;
        float* dst = sbuf + bsel*5508;
        for (int idx = tid; idx < 5184; idx += 256){
            int cell = idx >> 4, ch = idx & 15;
            int r = cell / 18, col = cell - r*18;
            int gh = bh + r - 1, gw = bw + col - 1;
            if ((unsigned)gh < HH && (unsigned)gw < WW){
                unsigned sa = (unsigned)__cvta_generic_to_shared(dst + cell*17 + ch);
                asm volatile("cp.async.ca.shared.global [%0], [%1], 4;\n"
                             :: "r"(sa), "l"(f + (size_t)(gh*WW+gw)*CC + c0 + ch));
            }
        }
        asm volatile("cp.async.commit_group;\n");
    };

    issue_chunk(0, 0);

    for (int ck = 0; ck < 8; ck++){
        asm volatile("cp.async.wait_group 0;\n" ::: "memory");
        __syncthreads();
        if (ck < 7) issue_chunk(ck+1, (ck+1)&1);

        const float* sb = sbuf + (ck&1)*5508;
        int c0 = ck*16;

        #pragma unroll
        for (int ch = 0; ch < 16; ch++){
            float v00 = sb[(base-19)*17+ch], v01 = sb[(base-18)*17+ch], v02 = sb[(base-17)*17+ch];
            float v10 = sb[(base- 1)*17+ch], v11 = sb[(base   )*17+ch], v12 = sb[(base+ 1)*17+ch];
            float v20 = sb[(base+17)*17+ch], v21 = sb[(base+18)*17+ch], v22 = sb[(base+19)*17+ch];
            float gx = (v02 - v00) + 2.0f*(v12 - v10) + (v22 - v20);
            float gy = (v20 - v00) + 2.0f*(v21 - v01) + (v22 - v02);
            geo += sqrtf(gx*gx + gy*gy);
            ownss   = fmaf(v11, v11, ownss);
            dot4[0] = fmaf(v11, v12, dot4[0]);
            dot4[1] = fmaf(v11, v20, dot4[1]);
            dot4[2] = fmaf(v11, v21, dot4[2]);
            dot4[3] = fmaf(v11, v22, dot4[3]);
            {
                unsigned long long f2 = pk2(v11, v11);
                const ulonglong2* wr = (const ulonglong2*)(sw + (c0 + ch)*32);
                #pragma unroll
                for (int q = 0; q < 8; q++){
                    ulonglong2 wv = wr[q];
                    fma2(macc[2*q  ], f2, wv.x);
                    fma2(macc[2*q+1], f2, wv.y);
                }
            }
            int c = c0 + ch;
            if (c >= 64){
                float xs = v00+v01+v02+v10+v11+v12+v20+v21+v22;
                float x2 = v00*v00+v01*v01+v02*v02+v10*v10+v11*v11+v12*v12+v20*v20+v21*v21+v22*v22;
                float m1 = xs * (1.0f/9.0f);
                var += x2 * (1.0f/9.0f) - m1*m1;
            } else {
                float d = v11 - sendlf[c];
                ab2 += d*d;
            }
        }
        if (tid < 49){
            const float* eb = sb + eidx*17;
            #pragma unroll
            for (int ch=0; ch<16; ch++) ess = fmaf(eb[ch], eb[ch], ess);
        }
    }

    int px = (bh+ty)*WW + (bw+tx);
    g_geo [px] = geo * (1.0f/128.0f);
    g_var [px] = var;
    g_abs2[px] = ab2;
    g_dist[0][px] = BIGF;
    g_dist[1][px] = BIGF;

    {
        float z = b2[0];
        #pragma unroll
        for (int j=0;j<16;j++){
            float2 u = upk2(macc[j]);
            z = fmaf(fmaxf(u.x, 0.0f), w2[2*j],   z);
            z = fmaf(fmaxf(u.y, 0.0f), w2[2*j+1], z);
        }
        g_omega[px] = 1.0f / (1.0f + expf(-z));
    }

    __syncthreads();
    snorm[base] = ownss;
    if (tid < 49) snorm[eidx] = ess;
    __syncthreads();

    int h = bh + ty, w = bw + tx;
    float invp = 1.0f / fmaxf(sqrtf(ownss), 1e-12f);
    const int nbo[4] = {1, 17, 18, 19};
    const int ddx[4] = {0,1,1,1};
    const int ddy[4] = {1,-1,0,1};
    #pragma unroll
    for (int d=0; d<4; d++){
        int i = 4 + d;
        int nh = h + ddx[d], nw = w + ddy[d];
        if ((unsigned)nh < HH && (unsigned)nw < WW){
            float nn = snorm[base + nbo[d]];
            float val = 1.0f - dot4[d] * invp / fmaxf(sqrtf(nn), 1e-12f);
            int npx = nh*WW + nw;
            g_cost[(size_t)px *8 + i]          = val;
            out   [(size_t)px *10 + 1 + i]     = val;
            g_cost[(size_t)npx*8 + (7-i)]      = val;
            out   [(size_t)npx*10 + 1 + (7-i)] = val;
        } else {
            g_cost[(size_t)px*8 + i]      = BIGF;
            out   [(size_t)px*10 + 1 + i] = BIGF;
        }
    }
    const int udx[4] = {-1,-1,-1, 0};
    const int udy[4] = {-1, 0, 1,-1};
    #pragma unroll
    for (int j=0; j<4; j++){
        int nh = h + udx[j], nw = w + udy[j];
        if (!((unsigned)nh < HH && (unsigned)nw < WW)){
            g_cost[(size_t)px*8 + j]      = BIGF;
            out   [(size_t)px*10 + 1 + j] = BIGF;
        }
    }
}

// ---------------- persistent relaxation: 16 phases x K=16, 128 blocks ----------
// Tile 16(h)x32(w), halo 16 -> region 48x64 (3072 cells). 768 threads, 2x2
// cells/thread. 128 blocks all resident at occ 1 -> global barrier safe.
// Active cone per iteration: rows [1+it,46-it], cols [1+it,62-it]; fringe
// writes never re-read (same invariant as the proven K=8 kernel).
__global__ void __launch_bounds__(768,1) dist_relax_persist(const int* __restrict__ startn,
                                                            const int* __restrict__ endn,
                                                            const float* __restrict__ dl,
                                                            const float* __restrict__ gm,
                                                            const float* __restrict__ bt,
                                                            float* __restrict__ out){
    __shared__ __align__(16) float sd[2][50][66];
    int tid = threadIdx.x;
    int tx2 = tid & 31, ty2 = tid >> 5;   // 24 x 32 thread grid
    int rr = 2*ty2, cc = 2*tx2;           // region row/col of top-left own cell
    int bh = blockIdx.y*16 - 16, bw = blockIdx.x*32 - 16;
    const unsigned NBLK = 128u;

    int sh = startn[0], sw_ = startn[1];
    int d0;
    {
        int rlo = max(bh, 0),  rhi = min(bh+47, HH-1);
        int clo = max(bw, 0),  chi = min(bw+63, WW-1);
        int dr = max(max(rlo - sh, sh - rhi), 0);
        int dc = max(max(clo - sw_, sw_ - chi), 0);
        d0 = max(dr, dc);
    }

    // frame init (never read by cone; defensive)
    for (int idx = tid; idx < 2*50*66; idx += 768){
        int l = idx / (50*66);
        int rem = idx % (50*66);
        int r = rem / 66, c = rem % 66;
        if (r == 0 || r == 49 || c == 0 || c == 65)
            sd[l][r][c] = BIGF;
    }

    // own-cell costs (4 cells), packed per row-pair
    unsigned long long cst2t[8], cst2b[8];
    {
        float cl[2][2][8];
        #pragma unroll
        for (int a=0;a<2;a++)
        #pragma unroll
        for (int b=0;b<2;b++){
            int gh = bh + rr + a, gw = bw + cc + b;
            if ((unsigned)gh < HH && (unsigned)gw < WW){
                const float4* cp = (const float4*)(g_cost + (size_t)(gh*WW+gw)*8);
                float4 u = __ldg(cp), w = __ldg(cp+1);
                cl[a][b][0]=u.x; cl[a][b][1]=u.y; cl[a][b][2]=u.z; cl[a][b][3]=u.w;
                cl[a][b][4]=w.x; cl[a][b][5]=w.y; cl[a][b][6]=w.z; cl[a][b][7]=w.w;
            } else {
                #pragma unroll
                for (int i=0;i<8;i++) cl[a][b][i] = BIGF;
            }
        }
        #pragma unroll
        for (int i=0;i<8;i++){
            cst2t[i] = pk2(cl[0][0][i], cl[0][1][i]);
            cst2b[i] = pk2(cl[1][0][i], cl[1][1][i]);
        }
    }

    // phase 0 base state (BIG except start)
    for (int idx = tid; idx < 3072; idx += 768){
        int r = idx >> 6, c = idx & 63;
        int gh = bh + r, gw = bw + c;
        sd[0][r+1][c+1] = (gh == sh && gw == sw_) ? 0.0f : BIGF;
    }

    bool is_store = (ty2 >= 8 && ty2 < 16 && tx2 >= 8 && tx2 < 24);
    int gh_s = bh + rr, gw_s = bw + cc;

    #pragma unroll 1
    for (int p = 0; p < 16; p++){
        float* __restrict__ dst = g_dist[(p+1) & 1];
        bool skip = (d0 > 16*(p+1));

        if (!skip){
            if (p > 0){
                const float* __restrict__ src = g_dist[p & 1];
                // reload halo ring (2560 cells); interior rows[16,31]xcols[16,47] retained
                for (int idx = tid; idx < 2560; idx += 768){
                    int r, c;
                    if (idx < 1024)      { r = idx >> 6;               c = idx & 63; }
                    else if (idx < 2048) { r = 32 + ((idx-1024) >> 6); c = idx & 63; }
                    else if (idx < 2304) { int t = idx-2048; r = 16 + (t >> 4); c = t & 15; }
                    else                 { int t = idx-2304; r = 16 + (t >> 4); c = 48 + (t & 15); }
                    int gh = bh + r, gw = bw + c;
                    float v = BIGF;
                    if ((unsigned)gh < HH && (unsigned)gw < WW)
                        v = __ldcg(src + gh*WW + gw);
                    sd[0][r+1][c+1] = v;
                }
            }
            __syncthreads();

            #pragma unroll
            for (int it = 0; it < 16; it++){
                const int cur = it & 1;
                bool colok = (cc+1 >= 1+it) && (cc <= 62-it);
                bool act_t = colok && (rr   >= 1+it) && (rr   <= 46-it);
                bool act_b = colok && (rr+1 >= 1+it) && (rr+1 <= 46-it);

                if (act_t | act_b){
                    // shared middle rows (sd rows rr+1, rr+2)
                    unsigned long long B0 = *(const unsigned long long*)&sd[cur][rr+1][cc];
                    unsigned long long B1 = *(const unsigned long long*)&sd[cur][rr+1][cc+2];
                    unsigned long long C0 = *(const unsigned long long*)&sd[cur][rr+2][cc];
                    unsigned long long C1 = *(const unsigned long long*)&sd[cur][rr+2][cc+2];
                    float2 fB0 = upk2(B0), fB1 = upk2(B1);
                    float2 fC0 = upk2(C0), fC1 = upk2(C1);
                    unsigned long long mixB = pk2(fB0.y, fB1.x);
                    unsigned long long mixC = pk2(fC0.y, fC1.x);

                    if (act_t){
                        unsigned long long A0 = *(const unsigned long long*)&sd[cur][rr][cc];
                        unsigned long long A1 = *(const unsigned long long*)&sd[cur][rr][cc+2];
                        float2 fA0 = upk2(A0), fA1 = upk2(A1);
                        unsigned long long mixA = pk2(fA0.y, fA1.x);

                        unsigned long long s0 = add2(A0,   cst2t[0]);
                        unsigned long long s1 = add2(mixA, cst2t[1]);
                        unsigned long long s2 = add2(A1,   cst2t[2]);
                        unsigned long long s3 = add2(B0,   cst2t[3]);
                        unsigned long long s4 = add2(B1,   cst2t[4]);
                        unsigned long long s5 = add2(C0,   cst2t[5]);
                        unsigned long long s6 = add2(mixC, cst2t[6]);
                        unsigned long long s7 = add2(C1,   cst2t[7]);
                        float2 u0=upk2(s0),u1=upk2(s1),u2=upk2(s2),u3=upk2(s3);
                        float2 u4=upk2(s4),u5=upk2(s5),u6=upk2(s6),u7=upk2(s7);
                        float v0 = fminf(fB0.y,
                                   fminf(fminf(fminf(u0.x,u1.x), fminf(u2.x,u3.x)),
                                         fminf(fminf(u4.x,u5.x), fminf(u6.x,u7.x))));
                        float v1 = fminf(fB1.x,
                                   fminf(fminf(fminf(u0.y,u1.y), fminf(u2.y,u3.y)),
                                         fminf(fminf(u4.y,u5.y), fminf(u6.y,u7.y))));
                        sd[cur^1][rr+1][cc+1] = v0;
                        sd[cur^1][rr+1][cc+2] = v1;
                    }
                    if (act_b){
                        unsigned long long D0 = *(const unsigned long long*)&sd[cur][rr+3][cc];
                        unsigned long long D1 = *(const unsigned long long*)&sd[cur][rr+3][cc+2];
                        float2 fD0 = upk2(D0), fD1 = upk2(D1);
                        unsigned long long mixD = pk2(fD0.y, fD1.x);

                        unsigned long long s0 = add2(B0,   cst2b[0]);
                        unsigned long long s1 = add2(mixB, cst2b[1]);
                        unsigned long long s2 = add2(B1,   cst2b[2]);
                        unsigned long long s3 = add2(C0,   cst2b[3]);
                        unsigned long long s4 = add2(C1,   cst2b[4]);
                        unsigned long long s5 = add2(D0,   cst2b[5]);
                        unsigned long long s6 = add2(mixD, cst2b[6]);
                        unsigned long long s7 = add2(D1,   cst2b[7]);
                        float2 u0=upk2(s0),u1=upk2(s1),u2=upk2(s2),u3=upk2(s3);
                        float2 u4=upk2(s4),u5=upk2(s5),u6=upk2(s6),u7=upk2(s7);
                        float v0 = fminf(fC0.y,
                                   fminf(fminf(fminf(u0.x,u1.x), fminf(u2.x,u3.x)),
                                         fminf(fminf(u4.x,u5.x), fminf(u6.x,u7.x))));
                        float v1 = fminf(fC1.x,
                                   fminf(fminf(fminf(u0.y,u1.y), fminf(u2.y,u3.y)),
                                         fminf(fminf(u4.y,u5.y), fminf(u6.y,u7.y))));
                        sd[cur^1][rr+2][cc+1] = v0;
                        sd[cur^1][rr+2][cc+2] = v1;
                    }
                }
                __syncthreads();
            }
            // 16 iterations (even) -> exact interior in sd[0], rows[16,31] cols[16,47]

            if (p < 15){
                if (is_store){
                    __stcg(dst + (gh_s  )*WW + gw_s,     sd[0][rr+1][cc+1]);
                    __stcg(dst + (gh_s  )*WW + gw_s + 1, sd[0][rr+1][cc+2]);
                    __stcg(dst + (gh_s+1)*WW + gw_s,     sd[0][rr+2][cc+1]);
                    __stcg(dst + (gh_s+1)*WW + gw_s + 1, sd[0][rr+2][cc+2]);
                }
                __threadfence();
            } else {
                // final phase: write output (heuristic + dist)
                if (is_store){
                    int e = endn[0]*WW + endn[1];
                    float varEnd = g_var[e];
                    float q0 = softplusf(*dl), q1 = softplusf(*gm), q2 = softplusf(*bt);
                    #pragma unroll
                    for (int a=0; a<2; a++)
                        #pragma unroll
                        for (int b=0; b<2; b++){
                            int px = (gh_s+a)*WW + gw_s + b;
                            float om = g_omega[px];
                            float hv = q0*g_geo[px]
                                     + om*q1*(varEnd - g_var[px])
                                     + (1.0f - om)*q2*sqrtf(g_abs2[px]);
                            out[(size_t)px*10 + 0] = fmaxf(hv, 0.0f);
                            out[(size_t)px*10 + 9] = fminf(sd[0][rr+1+a][cc+1+b], BIGF);
                        }
                }
            }
        }

        if (p < 15){
            __syncthreads();
            if (tid == 0){
                atomicAdd(&g_arrive, 1u);
                unsigned target = NBLK * (unsigned)(p + 1);
                while (*((volatile unsigned*)&g_arrive) < target) __nanosleep(64);
            }
            __syncthreads();
        }
    }
}

// ---------------- launch ----------------
extern "C" void kernel_launch(void* const* d_in, const int* in_sizes, int n_in,
                              void* d_out, int out_size){
    const float* f = (const float*)d_in[0];
    float* out = (float*)d_out;

    static int smem_set = 0;
    if (!smem_set){
        cudaFuncSetAttribute(hc_k, cudaFuncAttributeMaxDynamicSharedMemorySize, 62000);
        smem_set = 1;
    }

    hc_k<<<dim3(16,16), 256, 62000>>>(f, out, (const float*)d_in[4], (const float*)d_in[5],
                                      (const float*)d_in[6], (const float*)d_in[7],
                                      (const int*)d_in[9]);
    dist_relax_persist<<<dim3(8,16), 768>>>((const int*)d_in[8], (const int*)d_in[9],
                                            (const float*)d_in[1], (const float*)d_in[2],
                                            (const float*)d_in[3], out);
}